// round 14
// baseline (speedup 1.0000x reference)
#include <cuda_runtime.h>
#include <cuda_fp16.h>
#include <math.h>
#include <math_constants.h>
#include <cstdint>

// ---------------------------------------------------------------------------
// Problem constants
// ---------------------------------------------------------------------------
#define BB   2
#define QL   2048
#define KLEN 2048
#define DMOD 512
#define NH   8
#define NF   5
#define DH   64
#define NTAB 1024

static const float TAB_SCALE = (float)(NTAB - 1) / 14.2f;
#define LOG2E 1.4426950408889634f

// ---------------------------------------------------------------------------
// Device scratch
// ---------------------------------------------------------------------------
__device__ __half g_qp [BB * QL   * DMOD];
__device__ __half g_kp [BB * KLEN * DMOD];
__device__ __half g_vp [BB * KLEN * DMOD];
__device__ __half g_vpT[BB * DMOD * KLEN];
__device__ __half g_ctx[BB * QL   * DMOD];
__device__ __half g_rq [BB * QL   * DMOD];
__device__ __half g_rk [BB * KLEN * DMOD];
__device__ __half g_rv [BB * KLEN * DMOD];
__device__ __half g_rw [4][DMOD * DMOD];
__device__ float2 g_tab[NH * NTAB];

// ---------------------------------------------------------------------------
// Helpers
// ---------------------------------------------------------------------------
__device__ __forceinline__ uint32_t pack_f16x2(float lo, float hi) {
    uint32_t r;
    asm("cvt.rn.f16x2.f32 %0, %1, %2;" : "=r"(r) : "f"(hi), "f"(lo));
    return r;
}
__device__ __forceinline__ float ex2f(float x) {
    float r;
    asm("ex2.approx.f32 %0, %1;" : "=f"(r) : "f"(x));
    return r;
}
__device__ __forceinline__ uint32_t ex2h2(uint32_t x) {
    uint32_t r;
    asm("ex2.approx.f16x2 %0, %1;" : "=r"(r) : "r"(x));
    return r;
}
__device__ __forceinline__ float sqrt_ap(float x) {
    float r;
    asm("sqrt.approx.f32 %0, %1;" : "=f"(r) : "f"(x));
    return r;
}

__device__ __forceinline__ void mma_f16(float* c, const uint32_t* a,
                                        uint32_t b0, uint32_t b1) {
    asm volatile("mma.sync.aligned.m16n8k16.row.col.f32.f16.f16.f32 "
                 "{%0,%1,%2,%3}, {%4,%5,%6,%7}, {%8,%9}, {%0,%1,%2,%3};"
                 : "+f"(c[0]), "+f"(c[1]), "+f"(c[2]), "+f"(c[3])
                 : "r"(a[0]), "r"(a[1]), "r"(a[2]), "r"(a[3]),
                   "r"(b0), "r"(b1));
}

// ldmatrix x4: 4 8x8 fp16 matrices; thread lane>>3 selects matrix, lane&7 row.
__device__ __forceinline__ void ldmx4(uint32_t* r, uint32_t addr) {
    asm volatile("ldmatrix.sync.aligned.m8n8.x4.shared.b16 {%0,%1,%2,%3}, [%4];"
                 : "=r"(r[0]), "=r"(r[1]), "=r"(r[2]), "=r"(r[3])
                 : "r"(addr));
}

__device__ __forceinline__ uint32_t sptr(const void* p) {
    return (uint32_t)__cvta_generic_to_shared(p);
}
__device__ __forceinline__ void cp16(uint32_t smem_addr, const void* gptr) {
    asm volatile("cp.async.cg.shared.global [%0], [%1], 16;"
                 :: "r"(smem_addr), "l"(gptr) : "memory");
}
__device__ __forceinline__ void cp_commit() {
    asm volatile("cp.async.commit_group;" ::: "memory");
}
template <int N>
__device__ __forceinline__ void cp_wait() {
    asm volatile("cp.async.wait_group %0;" :: "n"(N) : "memory");
}

// ---------------------------------------------------------------------------
// Fused prep: round acts (0..3071), weights (3072..4095), table (4096..4127).
// ---------------------------------------------------------------------------
__global__ __launch_bounds__(256)
void prep_kernel(const float* __restrict__ qs, const float* __restrict__ ks,
                 const float* __restrict__ vs,
                 const float* __restrict__ Wq, const float* __restrict__ Wk,
                 const float* __restrict__ Wv, const float* __restrict__ Wo,
                 const float* __restrict__ Ap, const float* __restrict__ Bp,
                 const float* __restrict__ Cp)
{
    __shared__ float tw[32][33];
    const int blk = blockIdx.x;
    const int tid = threadIdx.x;

    if (blk < 3072) {
        const int z = blk >> 10;
        const int inner = blk & 1023;
        const float* src = (z == 0) ? qs : (z == 1) ? ks : vs;
        __half* dst = (z == 0) ? g_rq : (z == 1) ? g_rk : g_rv;
        size_t i = ((size_t)inner * 256 + tid) * 8;
        if (i >= (size_t)BB * QL * DMOD) return;
        float4 v0 = *(const float4*)&src[i];
        float4 v1 = *(const float4*)&src[i + 4];
        uint4 o;
        o.x = pack_f16x2(v0.x, v0.y);
        o.y = pack_f16x2(v0.z, v0.w);
        o.z = pack_f16x2(v1.x, v1.y);
        o.w = pack_f16x2(v1.z, v1.w);
        *(uint4*)&dst[i] = o;
    } else if (blk < 4096) {
        const int gidx = blk - 3072;
        const int z    = gidx >> 8;
        const int rest = gidx & 255;
        const float* W = (z == 0) ? Wq : (z == 1) ? Wk : (z == 2) ? Wv : Wo;
        __half* Wt = g_rw[z];
        const int bx = (rest & 15) * 32;
        const int by = (rest >> 4) * 32;
        const int tx = tid & 31;
        const int ty = tid >> 5;
#pragma unroll
        for (int i = 0; i < 32; i += 8)
            tw[ty + i][tx] = W[(size_t)(by + ty + i) * DMOD + bx + tx];
        __syncthreads();
#pragma unroll
        for (int i = 0; i < 32; i += 8)
            Wt[(size_t)(bx + ty + i) * DMOD + by + tx] = __float2half(tw[tx][ty + i]);
    } else {
        int idx = (blk - 4096) * 256 + tid;
        if (idx >= NH * NTAB) return;
        int h = idx >> 10;
        int i = idx & 1023;
        const float STEP = 14.2f / (float)(NTAB - 1);
        float d0 = (float)i * STEP;
        float d1 = d0 + STEP;
        float v0 = 0.f, v1 = 0.f;
#pragma unroll
        for (int f = 0; f < NF; f++) {
            float af = Ap[h * NF + f];
            float bf = fabsf(Bp[h * NF + f]);
            float cf = Cp[h * NF + f];
            float t0 = d0 - cf;
            float t1 = d1 - cf;
            v0 += af * expf(-bf * t0 * t0);
            v1 += af * expf(-bf * t1 * t1);
        }
        v0 *= LOG2E;
        v1 *= LOG2E;
        g_tab[idx] = make_float2(v0, v1 - v0);
    }
}

// ---------------------------------------------------------------------------
// V transpose (fp16)
// ---------------------------------------------------------------------------
__global__ __launch_bounds__(256)
void transpose_v_kernel()
{
    __shared__ __half t[64][72];
    const int b  = blockIdx.z;
    const int k0 = blockIdx.x * 64;
    const int d0 = blockIdx.y * 64;
    const int tid = threadIdx.x;
#pragma unroll
    for (int p = 0; p < 8; p++) {
        int e = tid + p * 256;
        int key = e >> 5;
        int dp  = e & 31;
        uint32_t v = *(const uint32_t*)&g_vp[((size_t)(b * KLEN + k0 + key)) * DMOD + d0 + 2 * dp];
        __half2 h2 = *(__half2*)&v;
        t[2 * dp    ][key] = __low2half(h2);
        t[2 * dp + 1][key] = __high2half(h2);
    }
    __syncthreads();
#pragma unroll
    for (int p = 0; p < 2; p++) {
        int e = tid + p * 256;
        int dm = e >> 3;
        int c  = e & 7;
        uint4 v = *(uint4*)&t[dm][c * 8];
        *(uint4*)&g_vpT[((size_t)(b * DMOD + d0 + dm)) * KLEN + k0 + c * 8] = v;
    }
}

// ---------------------------------------------------------------------------
// fp16 GEMM: 128x128, BK=32, 3-stage cp.async, ldmatrix frag loads.
// ---------------------------------------------------------------------------
#define GP 20
#define STG_U32 (128 * GP)
#define GSTAGES 3
#define GEMM_SMEM (GSTAGES * 2 * STG_U32 * 4)   // 61440 bytes

template <int MODE>
__device__ __forceinline__ void gemm_core(const __half* __restrict__ Ah,
                                          const __half* __restrict__ Wt,
                                          const float* __restrict__ bias,
                                          float scale,
                                          float* __restrict__ outF,
                                          __half* __restrict__ outH)
{
    extern __shared__ __align__(16) uint32_t dsm[];

    const int tid  = threadIdx.x;
    const int lane = tid & 31;
    const int wrp  = tid >> 5;
    const int m_off = (wrp >> 1) * 32;
    const int n_off = (wrp & 1) * 64;
    const int m0 = blockIdx.y * 128;
    const int n0 = blockIdx.x * 128;
    const int lq = lane >> 2;
    const int lr = lane & 3;

    const int mi   = lane >> 3;     // ldmatrix matrix index
    const int mrow = lane & 7;      // ldmatrix row within matrix

    const int ra = tid >> 1;
    const int ca = (tid & 1) * 2;

    float c[2][8][4];
#pragma unroll
    for (int i = 0; i < 2; i++)
#pragma unroll
        for (int j = 0; j < 8; j++)
#pragma unroll
            for (int e = 0; e < 4; e++) c[i][j][e] = 0.f;

#define GEMM_PREFETCH(CH, STG)                                                 \
    {                                                                          \
        uint32_t* A_s = dsm + (STG) * 2 * STG_U32;                             \
        uint32_t* B_s = A_s + STG_U32;                                         \
        const __half* Asrc = Ah + (size_t)(m0 + ra) * DMOD + (CH) * 32 + ca * 8; \
        cp16(sptr(&A_s[ra * GP + ca * 4]),     Asrc);                          \
        cp16(sptr(&A_s[ra * GP + ca * 4 + 4]), Asrc + 8);                      \
        const __half* Bsrc = Wt + (size_t)(n0 + ra) * DMOD + (CH) * 32 + ca * 8; \
        cp16(sptr(&B_s[ra * GP + ca * 4]),     Bsrc);                          \
        cp16(sptr(&B_s[ra * GP + ca * 4 + 4]), Bsrc + 8);                      \
        cp_commit();                                                           \
    }

    GEMM_PREFETCH(0, 0)
    GEMM_PREFETCH(1, 1)

    // ldmatrix per-thread address components (byte offsets, row stride 80B)
    const uint32_t a_rowsel = (uint32_t)((m_off + (mi & 1) * 8 + mrow) * 80 + (mi >> 1) * 16);
    const uint32_t b_rowsel = (uint32_t)((n_off + (mi >> 1) * 8 + mrow) * 80 + (mi & 1) * 16);

    int st = 0, pst = 2;
    for (int ch = 0; ch < 16; ch++) {
        if (ch < 15) cp_wait<1>(); else cp_wait<0>();
        __syncthreads();
        if (ch + 2 < 16) GEMM_PREFETCH(ch + 2, pst)

        const uint32_t sa = sptr(dsm + st * 2 * STG_U32);
        const uint32_t sb = sa + STG_U32 * 4;
#pragma unroll
        for (int ks = 0; ks < 2; ks++) {
            uint32_t a[2][4], b[4][4];
#pragma unroll
            for (int i = 0; i < 2; i++)
                ldmx4(a[i], sa + a_rowsel + i * 16 * 80 + ks * 32);
#pragma unroll
            for (int np = 0; np < 4; np++)
                ldmx4(b[np], sb + b_rowsel + np * 16 * 80 + ks * 32);
#pragma unroll
            for (int i = 0; i < 2; i++)
#pragma unroll
                for (int np = 0; np < 4; np++) {
                    mma_f16(c[i][2 * np    ], a[i], b[np][0], b[np][1]);
                    mma_f16(c[i][2 * np + 1], a[i], b[np][2], b[np][3]);
                }
        }
        st  = (st  == 2) ? 0 : st  + 1;
        pst = (pst == 2) ? 0 : pst + 1;
    }

#pragma unroll
    for (int i = 0; i < 2; i++) {
        int row = m0 + m_off + i * 16 + lq;
#pragma unroll
        for (int j = 0; j < 8; j++) {
            int col = n0 + n_off + j * 8 + 2 * lr;
            float b0 = bias[col], b1 = bias[col + 1];
            float v00 = (c[i][j][0] + b0) * scale;
            float v01 = (c[i][j][1] + b1) * scale;
            float v10 = (c[i][j][2] + b0) * scale;
            float v11 = (c[i][j][3] + b1) * scale;
            if (MODE == 0) {
                *(float2*)&outF[(size_t)row * DMOD + col] = make_float2(v00, v01);
                *(float2*)&outF[(size_t)(row + 8) * DMOD + col] = make_float2(v10, v11);
            } else {
                uint32_t* o32 = (uint32_t*)outH;
                o32[(size_t)row * (DMOD / 2) + (col >> 1)] = pack_f16x2(v00, v01);
                o32[(size_t)(row + 8) * (DMOD / 2) + (col >> 1)] = pack_f16x2(v10, v11);
            }
        }
    }
#undef GEMM_PREFETCH
}

__global__ __launch_bounds__(256, 3)
void gemm_qkv_kernel(const float* __restrict__ bq, const float* __restrict__ bk,
                     const float* __restrict__ bv)
{
    const int z = blockIdx.z;
    const __half* A = (z == 0) ? g_rq : (z == 1) ? g_rk : g_rv;
    const __half* W = g_rw[z];
    const float*  B = (z == 0) ? bq : (z == 1) ? bk : bv;
    __half*       C = (z == 0) ? g_qp : (z == 1) ? g_kp : g_vp;
    const float   s = (z == 0) ? 0.125f * LOG2E : 1.0f;
    gemm_core<1>(A, W, B, s, nullptr, C);
}

__global__ __launch_bounds__(256, 3)
void gemm_out_kernel(const float* __restrict__ bias, float* __restrict__ Cout)
{
    gemm_core<0>(g_ctx, g_rw[3], bias, 1.0f, Cout, nullptr);
}

// ---------------------------------------------------------------------------
// fp16 tensor-core flash attention; exp2 softmax; ldmatrix frag loads.
// ---------------------------------------------------------------------------
#define KT 64

__global__ __launch_bounds__(256, 2)
void attn_tc_kernel(const float* __restrict__ qlocs,
                    const float* __restrict__ klocs,
                    const int*   __restrict__ vlens)
{
    __shared__ __align__(16) uint32_t sK [2][KT * 36];
    __shared__ __align__(16) uint32_t sVT[2][KT * 36];
    __shared__ __align__(16) float2   tsh[NTAB];
    __shared__ __align__(16) float2   lsh[2][KT];

    const int b   = blockIdx.z;
    const int h   = blockIdx.y;
    const int q0  = blockIdx.x * 128;
    const int tid = threadIdx.x;
    const int lane = tid & 31;
    const int w    = tid >> 5;
    const int g    = lane >> 2;
    const int t    = lane & 3;
    const int r0   = w * 16 + g;

    const int mi   = lane >> 3;
    const int mrow = lane & 7;
    // ldmatrix row-select for 144B-stride tiles: matrices = (n-pair, chunk)
    const uint32_t f_rowsel = (uint32_t)(((mi >> 1) * 8 + mrow) * 144 + (mi & 1) * 16);

    for (int i = tid; i < NTAB; i += 256) tsh[i] = g_tab[h * NTAB + i];

    uint32_t qa[4][4];
    {
        const uint32_t* q32a = (const uint32_t*)(g_qp +
            (size_t)(b * QL + q0 + r0) * DMOD + h * DH);
        const uint32_t* q32b = q32a + 4 * DMOD;
#pragma unroll
        for (int ks = 0; ks < 4; ks++) {
            qa[ks][0] = __ldg(&q32a[8 * ks + t]);
            qa[ks][1] = __ldg(&q32b[8 * ks + t]);
            qa[ks][2] = __ldg(&q32a[8 * ks + t + 4]);
            qa[ks][3] = __ldg(&q32b[8 * ks + t + 4]);
        }
    }
    float2 ql0 = *(const float2*)&qlocs[((size_t)(b * QL + q0 + r0)) * 2];
    float2 ql1 = *(const float2*)&qlocs[((size_t)(b * QL + q0 + r0 + 8)) * 2];

    const int vlen  = vlens[b];
    const int nfull = vlen >> 6;
    const int rem   = vlen & 63;
    const int ntiles = nfull + (rem ? 1 : 0);

    float o[8][4];
#pragma unroll
    for (int n = 0; n < 8; n++)
#pragma unroll
        for (int e = 0; e < 4; e++) o[n][e] = 0.f;
    float m0 = -CUDART_INF_F, m1 = -CUDART_INF_F;
    float l0 = 0.f, l1 = 0.f;

    const __half* kgh = g_kp + (size_t)b * KLEN * DMOD + h * DH;
    const __half* vgh = g_vpT + ((size_t)(b * DMOD + h * DH)) * KLEN;

    const int kr = tid >> 2;
    const int kc = (tid & 3) * 2;

    {
        const __half* ks_ = kgh + (size_t)kr * DMOD + kc * 8;
        cp16(sptr(&sK[0][kr * 36 + kc * 4]),     ks_);
        cp16(sptr(&sK[0][kr * 36 + kc * 4 + 4]), ks_ + 8);
        const __half* vs_ = vgh + (size_t)kr * KLEN + kc * 8;
        cp16(sptr(&sVT[0][kr * 36 + kc * 4]),     vs_);
        cp16(sptr(&sVT[0][kr * 36 + kc * 4 + 4]), vs_ + 8);
        if (tid < 32)
            cp16(sptr(&lsh[0][0]) + tid * 16,
                 &klocs[((size_t)(b * KLEN)) * 2 + tid * 4]);
        cp_commit();
    }

    for (int tile = 0; tile < ntiles; tile++) {
        const int st = tile & 1;
        const int kb = tile * KT;
        cp_wait<0>();
        __syncthreads();
        if (tile + 1 < ntiles) {
            const int kb2 = kb + KT;
            const __half* ks_ = kgh + (size_t)(kb2 + kr) * DMOD + kc * 8;
            cp16(sptr(&sK[st ^ 1][kr * 36 + kc * 4]),     ks_);
            cp16(sptr(&sK[st ^ 1][kr * 36 + kc * 4 + 4]), ks_ + 8);
            const __half* vs_ = vgh + (size_t)kr * KLEN + kb2 + kc * 8;
            cp16(sptr(&sVT[st ^ 1][kr * 36 + kc * 4]),     vs_);
            cp16(sptr(&sVT[st ^ 1][kr * 36 + kc * 4 + 4]), vs_ + 8);
            if (tid < 32)
                cp16(sptr(&lsh[st ^ 1][0]) + tid * 16,
                     &klocs[((size_t)(b * KLEN + kb2)) * 2 + tid * 4]);
            cp_commit();
        }

        const uint32_t skb = sptr(sK[st]);
        const uint32_t svb = sptr(sVT[st]);
        const float2*  sl  = lsh[st];

        // ---- S = Q K^T (log2 units), ldmatrix b-frags ----
        float s[8][4];
#pragma unroll
        for (int n = 0; n < 8; n++)
#pragma unroll
            for (int e = 0; e < 4; e++) s[n][e] = 0.f;
#pragma unroll
        for (int ks = 0; ks < 4; ks++) {
            uint32_t bf[4][4];
#pragma unroll
            for (int np = 0; np < 4; np++)
                ldmx4(bf[np], skb + f_rowsel + np * 16 * 144 + ks * 32);
#pragma unroll
            for (int np = 0; np < 4; np++) {
                mma_f16(s[2 * np    ], qa[ks], bf[np][0], bf[np][1]);
                mma_f16(s[2 * np + 1], qa[ks], bf[np][2], bf[np][3]);
            }
        }

        // ---- bias + mask + tile row-max ----
        const bool edge = (rem != 0) && (tile == nfull);
        float tmax0 = -CUDART_INF_F, tmax1 = -CUDART_INF_F;
#pragma unroll
        for (int n = 0; n < 8; n++) {
            int c0 = n * 8 + 2 * t;
            float2 kl0 = sl[c0];
            float2 kl1 = sl[c0 + 1];
            float dx, dy, tp, fr;
            int ti;
            float2 tv;

            dx = ql0.x - kl0.x; dy = ql0.y - kl0.y;
            tp = sqrt_ap(fmaf(dx, dx, dy * dy)) * TAB_SCALE;
            ti = (int)tp; fr = tp - (float)ti;
            tv = tsh[ti];
            s[n][0] += fmaf(fr, tv.y, tv.x);

            dx = ql0.x - kl1.x; dy = ql0.y - kl1.y;
            tp = sqrt_ap(fmaf(dx, dx, dy * dy)) * TAB_SCALE;
            ti = (int)tp; fr = tp - (float)ti;
            tv = tsh[ti];
            s[n][1] += fmaf(fr, tv.y, tv.x);

            dx = ql1.x - kl0.x; dy = ql1.y - kl0.y;
            tp = sqrt_ap(fmaf(dx, dx, dy * dy)) * TAB_SCALE;
            ti = (int)tp; fr = tp - (float)ti;
            tv = tsh[ti];
            s[n][2] += fmaf(fr, tv.y, tv.x);

            dx = ql1.x - kl1.x; dy = ql1.y - kl1.y;
            tp = sqrt_ap(fmaf(dx, dx, dy * dy)) * TAB_SCALE;
            ti = (int)tp; fr = tp - (float)ti;
            tv = tsh[ti];
            s[n][3] += fmaf(fr, tv.y, tv.x);

            if (edge) {
                if (kb + c0     >= vlen) { s[n][0] = -CUDART_INF_F; s[n][2] = -CUDART_INF_F; }
                if (kb + c0 + 1 >= vlen) { s[n][1] = -CUDART_INF_F; s[n][3] = -CUDART_INF_F; }
            }
            tmax0 = fmaxf(tmax0, fmaxf(s[n][0], s[n][1]));
            tmax1 = fmaxf(tmax1, fmaxf(s[n][2], s[n][3]));
        }
        tmax0 = fmaxf(tmax0, __shfl_xor_sync(0xffffffffu, tmax0, 1));
        tmax0 = fmaxf(tmax0, __shfl_xor_sync(0xffffffffu, tmax0, 2));
        tmax1 = fmaxf(tmax1, __shfl_xor_sync(0xffffffffu, tmax1, 1));
        tmax1 = fmaxf(tmax1, __shfl_xor_sync(0xffffffffu, tmax1, 2));

        // ---- online softmax via exp2, conditional rescale ----
        float mn0 = fmaxf(m0, tmax0), mn1 = fmaxf(m1, tmax1);
        float dm0 = m0 - mn0, dm1 = m1 - mn1;
        m0 = mn0; m1 = mn1;
        if (__any_sync(0xffffffffu, fminf(dm0, dm1) < 0.f)) {
            float cor0 = ex2f(dm0), cor1 = ex2f(dm1);
            l0 *= cor0; l1 *= cor1;
#pragma unroll
            for (int n = 0; n < 8; n++) {
                o[n][0] *= cor0; o[n][1] *= cor0;
                o[n][2] *= cor1; o[n][3] *= cor1;
            }
        }

        uint32_t pA[8], pB[8];
        __half2 rsa = __float2half2_rn(0.f), rsb = __float2half2_rn(0.f);
#pragma unroll
        for (int n = 0; n < 8; n++) {
            pA[n] = ex2h2(pack_f16x2(s[n][0] - mn0, s[n][1] - mn0));
            pB[n] = ex2h2(pack_f16x2(s[n][2] - mn1, s[n][3] - mn1));
            rsa = __hadd2(rsa, *(__half2*)&pA[n]);
            rsb = __hadd2(rsb, *(__half2*)&pB[n]);
        }
        float2 fa = __half22float2(rsa);
        float2 fb = __half22float2(rsb);
        float rs0 = fa.x + fa.y;
        float rs1 = fb.x + fb.y;
        rs0 += __shfl_xor_sync(0xffffffffu, rs0, 1);
        rs0 += __shfl_xor_sync(0xffffffffu, rs0, 2);
        rs1 += __shfl_xor_sync(0xffffffffu, rs1, 1);
        rs1 += __shfl_xor_sync(0xffffffffu, rs1, 2);
        l0 += rs0;
        l1 += rs1;

        // ---- O += P V : ldmatrix b-frags from V^T ----
#pragma unroll
        for (int ks = 0; ks < 4; ks++) {
            uint32_t pa[4];
            pa[0] = pA[2 * ks];
            pa[1] = pB[2 * ks];
            pa[2] = pA[2 * ks + 1];
            pa[3] = pB[2 * ks + 1];
            uint32_t bf[4][4];
#pragma unroll
            for (int np = 0; np < 4; np++)
                ldmx4(bf[np], svb + f_rowsel + np * 16 * 144 + ks * 32);
#pragma unroll
            for (int np = 0; np < 4; np++) {
                mma_f16(o[2 * np    ], pa, bf[np][0], bf[np][1]);
                mma_f16(o[2 * np + 1], pa, bf[np][2], bf[np][3]);
            }
        }
    }

    float inv0 = 1.0f / l0;
    float inv1 = 1.0f / l1;
    uint32_t* ctx32 = (uint32_t*)(g_ctx +
        (size_t)(b * QL + q0 + r0) * DMOD + h * DH);
    uint32_t* ctx32b = ctx32 + 4 * DMOD;
#pragma unroll
    for (int n = 0; n < 8; n++) {
        ctx32 [4 * n + t] = pack_f16x2(o[n][0] * inv0, o[n][1] * inv0);
        ctx32b[4 * n + t] = pack_f16x2(o[n][2] * inv1, o[n][3] * inv1);
    }
}

// ---------------------------------------------------------------------------
// Launch
// ---------------------------------------------------------------------------
extern "C" void kernel_launch(void* const* d_in, const int* in_sizes, int n_in,
                              void* d_out, int out_size)
{
    const float* qs    = (const float*)d_in[0];
    const float* ks    = (const float*)d_in[1];
    const float* vs    = (const float*)d_in[2];
    const float* qlocs = (const float*)d_in[3];
    const float* klocs = (const float*)d_in[4];
    const float* Wq    = (const float*)d_in[5];
    const float* bq    = (const float*)d_in[6];
    const float* Wk    = (const float*)d_in[7];
    const float* bk    = (const float*)d_in[8];
    const float* Wv    = (const float*)d_in[9];
    const float* bv    = (const float*)d_in[10];
    const float* Wo    = (const float*)d_in[11];
    const float* bo    = (const float*)d_in[12];
    const float* ap    = (const float*)d_in[13];
    const float* bp    = (const float*)d_in[14];
    const float* cp    = (const float*)d_in[15];
    const int*   vl    = (const int*)  d_in[16];
    float* out = (float*)d_out;

    static bool attr_set = false;
    if (!attr_set) {
        cudaFuncSetAttribute(gemm_qkv_kernel,
                             cudaFuncAttributeMaxDynamicSharedMemorySize, GEMM_SMEM);
        cudaFuncSetAttribute(gemm_out_kernel,
                             cudaFuncAttributeMaxDynamicSharedMemorySize, GEMM_SMEM);
        attr_set = true;
    }

    prep_kernel<<<4128, 256>>>(qs, ks, vs, Wq, Wk, Wv, Wo, ap, bp, cp);

    dim3 g3(DMOD / 128, (BB * QL) / 128, 3);
    gemm_qkv_kernel<<<g3, 256, GEMM_SMEM>>>(bq, bk, bv);

    dim3 tvg(KLEN / 64, DMOD / 64, BB);
    transpose_v_kernel<<<tvg, 256>>>();

    dim3 agrid(QL / 128, NH, BB);
    attn_tc_kernel<<<agrid, 256>>>(qlocs, klocs, vl);

    dim3 ggrid(DMOD / 128, (BB * QL) / 128);
    gemm_out_kernel<<<ggrid, 256, GEMM_SMEM>>>(bo, out);
}